// round 4
// baseline (speedup 1.0000x reference)
#include <cuda_runtime.h>
#include <math.h>

#define HN   16
#define KVN  8
#define HDIM 64
#define WIN  512
#define BATCH 2
#define SEQ  2048
#define DM   1024

// Scratch — layouts:
// g_q: [B, HN, S, 64], g_k/g_v: [B, KVN, S, 64], g_attn: [B*S, HN*64]
__device__ float g_q[(size_t)BATCH * HN * SEQ * HDIM];
__device__ float g_k[(size_t)BATCH * KVN * SEQ * HDIM];
__device__ float g_v[(size_t)BATCH * KVN * SEQ * HDIM];
__device__ float g_attn[(size_t)BATCH * SEQ * HN * HDIM];

// ---------------------------------------------------------------------------
// DIAGNOSTIC-SIMPLE GEMM: C = A[M,K] @ B[K,N], one thread per output element.
// No smem, no vector loads, no tiling. MODE 0: linear C. MODE 1: scatter to
// [B, NH, S, 64] head layout.
// ---------------------------------------------------------------------------
template <int MODE>
__global__ void __launch_bounds__(256)
sgemm(const float* __restrict__ A, const float* __restrict__ B,
      float* __restrict__ C, int M, int N, int K, int NH)
{
    const int n = blockIdx.x * 256 + threadIdx.x;
    const int m = blockIdx.y;
    if (n >= N || m >= M) return;

    const float* a = A + (size_t)m * K;
    float acc0 = 0.f, acc1 = 0.f, acc2 = 0.f, acc3 = 0.f;
    for (int k = 0; k < K; k += 4) {
        acc0 += a[k + 0] * B[(size_t)(k + 0) * N + n];
        acc1 += a[k + 1] * B[(size_t)(k + 1) * N + n];
        acc2 += a[k + 2] * B[(size_t)(k + 2) * N + n];
        acc3 += a[k + 3] * B[(size_t)(k + 3) * N + n];
    }
    const float acc = (acc0 + acc1) + (acc2 + acc3);

    if (MODE == 0) {
        C[(size_t)m * N + n] = acc;
    } else {
        const int b = m / SEQ, s = m % SEQ;
        const int h = n >> 6, d = n & 63;
        C[(((size_t)(b * NH + h)) * SEQ + s) * HDIM + d] = acc;
    }
}

// ---------------------------------------------------------------------------
// DIAGNOSTIC-SIMPLE RoPE: one thread per (row, s); double-precision trig so
// any fast-math float trig/pow degradation is ruled out.
// x layout: [rows, SEQ, 64].
// ---------------------------------------------------------------------------
__global__ void rope_simple(float* __restrict__ x, int rows)
{
    const int idx = blockIdx.x * blockDim.x + threadIdx.x;
    if (idx >= rows * SEQ) return;
    const int s = idx % SEQ;
    float* base = x + (size_t)idx * HDIM;

    for (int p = 0; p < 32; p++) {
        const double invf = pow(10000.0, -((double)(2 * p)) / 64.0);
        const double ang = (double)s * invf;
        const float c  = (float)cos(ang);
        const float sn = (float)sin(ang);
        const float x1 = base[p];
        const float x2 = base[p + 32];
        base[p]      = x1 * c - x2 * sn;
        base[p + 32] = x2 * c + x1 * sn;
    }
}

// ---------------------------------------------------------------------------
// Attention (UNCHANGED from R3 — the controlled variable).
// Row-per-thread: block = 64 threads = one 64-query tile.
// ---------------------------------------------------------------------------
__global__ void __launch_bounds__(64) attn_kernel()
{
    __shared__ float Ks[64][68];
    __shared__ float Vs[64][68];

    const int b = blockIdx.z, h = blockIdx.y;
    const int qb = blockIdx.x * 64;
    const int kvh = h >> 1;            // n_rep = 2
    const int tid = threadIdx.x;
    const int qi = qb + tid;

    const float* qg = g_q + ((size_t)(b * HN + h) * SEQ + qb) * HDIM;
    const float* kg = g_k + (size_t)(b * KVN + kvh) * SEQ * HDIM;
    const float* vg = g_v + (size_t)(b * KVN + kvh) * SEQ * HDIM;

    for (int i = tid; i < 64 * 16; i += 64) {
        const int f = i * 4;
        *(float4*)(&Ks[f >> 6][f & 63]) = *(const float4*)(qg + f);
    }
    __syncthreads();
    float4 q4[16];
#pragma unroll
    for (int d = 0; d < 16; d++) q4[d] = *(float4*)(&Ks[tid][d * 4]);
    __syncthreads();

    float4 av[16];
#pragma unroll
    for (int d = 0; d < 16; d++) av[d] = make_float4(0.f, 0.f, 0.f, 0.f);
    float m = -1e30f, l = 0.0f;

    const int kstart = (qb >= WIN) ? (qb - WIN) : 0;

    for (int kb = kstart; kb <= qb; kb += 64) {
        for (int i = tid; i < 64 * 16; i += 64) {
            const int f = i * 4;
            *(float4*)(&Ks[f >> 6][f & 63]) = *(const float4*)(kg + (size_t)kb * HDIM + f);
            *(float4*)(&Vs[f >> 6][f & 63]) = *(const float4*)(vg + (size_t)kb * HDIM + f);
        }
        __syncthreads();

        for (int j = 0; j < 64; j++) {
            const int kj = kb + j;
            float s0 = 0.f, s1 = 0.f, s2 = 0.f, s3 = 0.f;
#pragma unroll
            for (int d = 0; d < 16; d++) {
                const float4 kk = *(const float4*)(&Ks[j][d * 4]);
                s0 += q4[d].x * kk.x;
                s1 += q4[d].y * kk.y;
                s2 += q4[d].z * kk.z;
                s3 += q4[d].w * kk.w;
            }
            float s = (s0 + s1) + (s2 + s3);

            if ((kj <= qi) && (kj + WIN >= qi)) {
                s *= 0.125f;
                if (s > m) {
                    const float alpha = __expf(m - s);
                    l *= alpha;
#pragma unroll
                    for (int d = 0; d < 16; d++) {
                        av[d].x *= alpha; av[d].y *= alpha;
                        av[d].z *= alpha; av[d].w *= alpha;
                    }
                    m = s;
                }
                const float p = __expf(s - m);
                l += p;
#pragma unroll
                for (int d = 0; d < 16; d++) {
                    const float4 vv = *(const float4*)(&Vs[j][d * 4]);
                    av[d].x += p * vv.x; av[d].y += p * vv.y;
                    av[d].z += p * vv.z; av[d].w += p * vv.w;
                }
            }
        }
        __syncthreads();
    }

    const float inv = 1.0f / l;
    float* og = g_attn + ((size_t)(b * SEQ + qi) * HN + h) * HDIM;
#pragma unroll
    for (int d = 0; d < 16; d++) {
        float4 o = make_float4(av[d].x * inv, av[d].y * inv,
                               av[d].z * inv, av[d].w * inv);
        *(float4*)(og + d * 4) = o;
    }
}

// ---------------------------------------------------------------------------
extern "C" void kernel_launch(void* const* d_in, const int* in_sizes, int n_in,
                              void* d_out, int out_size)
{
    // Positional mapping (metadata order = setup_inputs order), same as all
    // previous rounds — controlled variable.
    const float* hs = (const float*)d_in[0];
    const float* Wq = (const float*)d_in[1];
    const float* Wk = (const float*)d_in[2];
    const float* Wv = (const float*)d_in[3];
    const float* Wo = (const float*)d_in[4];
    float* out = (float*)d_out;

    float *qp, *kp, *vp, *ap;
    cudaGetSymbolAddress((void**)&qp, g_q);
    cudaGetSymbolAddress((void**)&kp, g_k);
    cudaGetSymbolAddress((void**)&vp, g_v);
    cudaGetSymbolAddress((void**)&ap, g_attn);

    const int M = BATCH * SEQ;   // 4096

    // QKV projections (scalar GEMM, scatter into head layout)
    sgemm<1><<<dim3((HN * HDIM) / 256, M), 256>>>(hs, Wq, qp, M, HN * HDIM, DM, HN);
    sgemm<1><<<dim3((KVN * HDIM) / 256, M), 256>>>(hs, Wk, kp, M, KVN * HDIM, DM, KVN);
    sgemm<1><<<dim3((KVN * HDIM) / 256, M), 256>>>(hs, Wv, vp, M, KVN * HDIM, DM, KVN);

    // RoPE (double-precision trig)
    rope_simple<<<(BATCH * HN * SEQ + 255) / 256, 256>>>(qp, BATCH * HN);
    rope_simple<<<(BATCH * KVN * SEQ + 255) / 256, 256>>>(kp, BATCH * KVN);

    // Attention (unchanged)
    attn_kernel<<<dim3(SEQ / 64, HN, BATCH), 64>>>();

    // Output projection
    sgemm<0><<<dim3(DM / 256, M), 256>>>(ap, Wo, out, M, DM, DM, 0);
}

// round 6
// speedup vs baseline: 4.0236x; 4.0236x over previous
#include <cuda_runtime.h>
#include <math.h>

#define HN   16
#define KVN  8
#define HDIM 64
#define WIN  512
#define BATCH 2
#define SEQ  2048
#define DM   1024

// Scratch — layouts:
// g_q: [B, HN, S, 64], g_k/g_v: [B, KVN, S, 64], g_attn: [B*S, HN*64]
__device__ float g_q[(size_t)BATCH * HN * SEQ * HDIM];
__device__ float g_k[(size_t)BATCH * KVN * SEQ * HDIM];
__device__ float g_v[(size_t)BATCH * KVN * SEQ * HDIM];
__device__ float g_attn[(size_t)BATCH * SEQ * HN * HDIM];
// RoPE tables: [SEQ][32] (pair p uses angle s * 10000^(-2p/64))
__device__ float g_cos[SEQ * 32];
__device__ float g_sin[SEQ * 32];

// ---------------------------------------------------------------------------
// Build RoPE table with double-precision trig (immune to --use_fast_math).
// One thread per (s, p).
// ---------------------------------------------------------------------------
__global__ void build_rope_table()
{
    const int idx = blockIdx.x * blockDim.x + threadIdx.x;
    if (idx >= SEQ * 32) return;
    const int p = idx & 31;
    const int s = idx >> 5;
    const double invf = pow(10000.0, -((double)(2 * p)) / 64.0);
    const double ang = (double)s * invf;
    g_cos[idx] = (float)cos(ang);
    g_sin[idx] = (float)sin(ang);
}

// ---------------------------------------------------------------------------
// RoPE apply from table. x: [rows, SEQ, 64]; one thread per (row, s, p<32).
// ---------------------------------------------------------------------------
__global__ void rope_apply(float* __restrict__ x, int rows)
{
    const int idx = blockIdx.x * blockDim.x + threadIdx.x;
    if (idx >= rows * SEQ * 32) return;
    const int p = idx & 31;
    const int s = (idx >> 5) & (SEQ - 1);

    const float c  = g_cos[(s << 5) | p];
    const float sn = g_sin[(s << 5) | p];

    float* base = x + (size_t)(idx >> 5) * HDIM;  // (row*SEQ + s) * 64
    const float x1 = base[p];
    const float x2 = base[p + 32];
    base[p]      = x1 * c - x2 * sn;
    base[p + 32] = x2 * c + x1 * sn;
}

// ---------------------------------------------------------------------------
// Tiled fp32 GEMM: C = A[M,K] @ B[K,N].  BM=BN=64, BK=16, 256 threads, 4x4/thr.
// MODE 0: linear row-major C.  MODE 1: scatter to [B, NH, S, 64] head layout.
// ---------------------------------------------------------------------------
template <int MODE>
__global__ void __launch_bounds__(256)
gemm64(const float* __restrict__ A, const float* __restrict__ Bm,
       float* __restrict__ C, int M, int N, int K, int NHEADS)
{
    __shared__ float As[16][68];
    __shared__ float Bs[16][64];

    const int tid = threadIdx.x;
    const int tx = tid & 15, ty = tid >> 4;
    const int m0 = blockIdx.y * 64, n0 = blockIdx.x * 64;

    const int ar = tid >> 2;
    const int ak = (tid & 3) * 4;
    const int br = tid >> 4;
    const int bc = (tid & 15) * 4;

    float acc[4][4] = {};

    for (int k0 = 0; k0 < K; k0 += 16) {
        float4 av = *(const float4*)(A + (size_t)(m0 + ar) * K + k0 + ak);
        As[ak + 0][ar] = av.x; As[ak + 1][ar] = av.y;
        As[ak + 2][ar] = av.z; As[ak + 3][ar] = av.w;
        *(float4*)(&Bs[br][bc]) =
            *(const float4*)(Bm + (size_t)(k0 + br) * N + n0 + bc);
        __syncthreads();

#pragma unroll
        for (int kk = 0; kk < 16; kk++) {
            const float a0 = As[kk][ty * 4 + 0];
            const float a1 = As[kk][ty * 4 + 1];
            const float a2 = As[kk][ty * 4 + 2];
            const float a3 = As[kk][ty * 4 + 3];
            const float4 bv = *(const float4*)(&Bs[kk][tx * 4]);
            acc[0][0] += a0 * bv.x; acc[0][1] += a0 * bv.y;
            acc[0][2] += a0 * bv.z; acc[0][3] += a0 * bv.w;
            acc[1][0] += a1 * bv.x; acc[1][1] += a1 * bv.y;
            acc[1][2] += a1 * bv.z; acc[1][3] += a1 * bv.w;
            acc[2][0] += a2 * bv.x; acc[2][1] += a2 * bv.y;
            acc[2][2] += a2 * bv.z; acc[2][3] += a2 * bv.w;
            acc[3][0] += a3 * bv.x; acc[3][1] += a3 * bv.y;
            acc[3][2] += a3 * bv.z; acc[3][3] += a3 * bv.w;
        }
        __syncthreads();
    }

    if (MODE == 0) {
#pragma unroll
        for (int i = 0; i < 4; i++) {
            float4 o = make_float4(acc[i][0], acc[i][1], acc[i][2], acc[i][3]);
            *(float4*)(C + (size_t)(m0 + ty * 4 + i) * N + n0 + tx * 4) = o;
        }
    } else {
        const int bb = m0 / SEQ;
        const int s0 = m0 % SEQ;
        const int hh = n0 >> 6;
        float* outp = C + ((size_t)(bb * NHEADS + hh) * SEQ + s0) * HDIM;
#pragma unroll
        for (int i = 0; i < 4; i++) {
            float4 o = make_float4(acc[i][0], acc[i][1], acc[i][2], acc[i][3]);
            *(float4*)(outp + (size_t)(ty * 4 + i) * HDIM + tx * 4) = o;
        }
    }
}

// ---------------------------------------------------------------------------
// Attention (validated): row-per-thread, 64 threads = one 64-query tile.
// ---------------------------------------------------------------------------
__global__ void __launch_bounds__(64) attn_kernel()
{
    __shared__ float Ks[64][68];
    __shared__ float Vs[64][68];

    const int b = blockIdx.z, h = blockIdx.y;
    const int qb = blockIdx.x * 64;
    const int kvh = h >> 1;            // n_rep = 2
    const int tid = threadIdx.x;
    const int qi = qb + tid;

    const float* qg = g_q + ((size_t)(b * HN + h) * SEQ + qb) * HDIM;
    const float* kg = g_k + (size_t)(b * KVN + kvh) * SEQ * HDIM;
    const float* vg = g_v + (size_t)(b * KVN + kvh) * SEQ * HDIM;

    for (int i = tid; i < 64 * 16; i += 64) {
        const int f = i * 4;
        *(float4*)(&Ks[f >> 6][f & 63]) = *(const float4*)(qg + f);
    }
    __syncthreads();
    float4 q4[16];
#pragma unroll
    for (int d = 0; d < 16; d++) q4[d] = *(float4*)(&Ks[tid][d * 4]);
    __syncthreads();

    float4 av[16];
#pragma unroll
    for (int d = 0; d < 16; d++) av[d] = make_float4(0.f, 0.f, 0.f, 0.f);
    float m = -1e30f, l = 0.0f;

    const int kstart = (qb >= WIN) ? (qb - WIN) : 0;

    for (int kb = kstart; kb <= qb; kb += 64) {
        for (int i = tid; i < 64 * 16; i += 64) {
            const int f = i * 4;
            *(float4*)(&Ks[f >> 6][f & 63]) = *(const float4*)(kg + (size_t)kb * HDIM + f);
            *(float4*)(&Vs[f >> 6][f & 63]) = *(const float4*)(vg + (size_t)kb * HDIM + f);
        }
        __syncthreads();

        for (int j = 0; j < 64; j++) {
            const int kj = kb + j;
            float s0 = 0.f, s1 = 0.f, s2 = 0.f, s3 = 0.f;
#pragma unroll
            for (int d = 0; d < 16; d++) {
                const float4 kk = *(const float4*)(&Ks[j][d * 4]);
                s0 += q4[d].x * kk.x;
                s1 += q4[d].y * kk.y;
                s2 += q4[d].z * kk.z;
                s3 += q4[d].w * kk.w;
            }
            float s = (s0 + s1) + (s2 + s3);

            if ((kj <= qi) && (kj + WIN >= qi)) {
                s *= 0.125f;
                if (s > m) {
                    const float alpha = __expf(m - s);
                    l *= alpha;
#pragma unroll
                    for (int d = 0; d < 16; d++) {
                        av[d].x *= alpha; av[d].y *= alpha;
                        av[d].z *= alpha; av[d].w *= alpha;
                    }
                    m = s;
                }
                const float p = __expf(s - m);
                l += p;
#pragma unroll
                for (int d = 0; d < 16; d++) {
                    const float4 vv = *(const float4*)(&Vs[j][d * 4]);
                    av[d].x += p * vv.x; av[d].y += p * vv.y;
                    av[d].z += p * vv.z; av[d].w += p * vv.w;
                }
            }
        }
        __syncthreads();
    }

    const float inv = 1.0f / l;
    float* og = g_attn + ((size_t)(b * SEQ + qi) * HN + h) * HDIM;
#pragma unroll
    for (int d = 0; d < 16; d++) {
        float4 o = make_float4(av[d].x * inv, av[d].y * inv,
                               av[d].z * inv, av[d].w * inv);
        *(float4*)(og + d * 4) = o;
    }
}

// ---------------------------------------------------------------------------
extern "C" void kernel_launch(void* const* d_in, const int* in_sizes, int n_in,
                              void* d_out, int out_size)
{
    const float* hs = (const float*)d_in[0];
    const float* Wq = (const float*)d_in[1];
    const float* Wk = (const float*)d_in[2];
    const float* Wv = (const float*)d_in[3];
    const float* Wo = (const float*)d_in[4];
    float* out = (float*)d_out;

    float *qp, *kp, *vp, *ap;
    cudaGetSymbolAddress((void**)&qp, g_q);
    cudaGetSymbolAddress((void**)&kp, g_k);
    cudaGetSymbolAddress((void**)&vp, g_v);
    cudaGetSymbolAddress((void**)&ap, g_attn);

    const int M = BATCH * SEQ;   // 4096
    dim3 blk(256);

    build_rope_table<<<(SEQ * 32) / 256, 256>>>();

    // QKV projections (tiled GEMM, scatter into head layout)
    gemm64<1><<<dim3(HN, M / 64), blk>>>(hs, Wq, qp, M, HN * HDIM, DM, HN);
    gemm64<1><<<dim3(KVN, M / 64), blk>>>(hs, Wk, kp, M, KVN * HDIM, DM, KVN);
    gemm64<1><<<dim3(KVN, M / 64), blk>>>(hs, Wv, vp, M, KVN * HDIM, DM, KVN);

    // RoPE from precomputed table
    rope_apply<<<(BATCH * HN * SEQ * 32) / 256, 256>>>(qp, BATCH * HN);
    rope_apply<<<(BATCH * KVN * SEQ * 32) / 256, 256>>>(kp, BATCH * KVN);

    // Attention
    attn_kernel<<<dim3(SEQ / 64, HN, BATCH), 64>>>();

    // Output projection
    gemm64<0><<<dim3(DM / 64, M / 64), blk>>>(ap, Wo, out, M, DM, DM, 0);
}